// round 17
// baseline (speedup 1.0000x reference)
#include <cuda_runtime.h>
#include <cuda_bf16.h>
#include <cuda_fp16.h>

#define NG 2048
#define HW 128
#define TANFOV 0.5f
#define NEARP 0.2f
#define AMIN (1.0f/255.0f)
#define LOG2E 1.4426950408889634f
#define CHUNKS 16             // z-buckets: z in [2+0.25k, 2+0.25(k+1))
#define NTILE 64              // 16x16 tiles (8x8 grid)
#define NCTA2 (NTILE*CHUNKS)  // 1024 blend CTAs, one per (tile,bucket) list
#define LCAP 64               // per-(tile,bucket) list capacity (mean ~9)

// per-gaussian blend data, indexed by ORIGINAL index
__device__ float4 g_p[NG];    // px, py, ca2, cb2
__device__ float4 g_q[NG];    // cc2, op, half2(colR,colG) bits, colB
// per-(tile,bucket) survivor lists, built by prep (order nondeterministic; key sorts)
__device__ unsigned long long g_list[NCTA2][LCAP];  // (zbits<<32)|idx
__device__ unsigned g_lcnt[NCTA2];                  // reset by last blend CTA
// per-bucket partial (r,g,b,T) per pixel
__device__ float4 g_part[CHUNKS][HW*HW];
// monotonic counters (graph-replay safe)
__device__ unsigned g_tile_cnt[NTILE];
__device__ unsigned g_done;

__device__ __forceinline__ float fast_exp2(float x) {
    float r;
    asm("ex2.approx.f32 %0, %1;" : "=f"(r) : "f"(x));
    return r;
}

__device__ __forceinline__ unsigned half2_bits(__half2 h) {
    __half2_raw hr = *reinterpret_cast<__half2_raw*>(&h);
    return (unsigned)hr.x | ((unsigned)hr.y << 16);
}

__device__ __forceinline__ __half2 bits_half2(unsigned u) {
    __half2_raw hr;
    hr.x = (unsigned short)(u & 0xFFFFu);
    hr.y = (unsigned short)(u >> 16);
    return *reinterpret_cast<__half2*>(&hr);
}

// ===== Kernel 1: preprocess + per-(tile,bucket) binning (8 x 256) =====
__global__ void __launch_bounds__(256) prep_kernel(
        const float* __restrict__ means3D,
        const float* __restrict__ colors,
        const float* __restrict__ opacities,
        const float* __restrict__ cov3Ds,
        float* __restrict__ out_radii) {
    int i = blockIdx.x * 256 + threadIdx.x;

    const float fx = HW / (2.0f * TANFOV);
    const float fy = fx;

    float x = __ldg(&means3D[3*i + 0]);
    float y = __ldg(&means3D[3*i + 1]);
    float z = __ldg(&means3D[3*i + 2]);
    float invz = 1.0f / z;

    float px = fx * x * invz + 0.5f * HW;
    float py = fy * y * invz + 0.5f * HW;

    const float lim = 1.3f * TANFOV;
    float txn = fminf(fmaxf(x * invz, -lim), lim) * z;
    float tyn = fminf(fmaxf(y * invz, -lim), lim) * z;

    float xx = __ldg(&cov3Ds[6*i+0]), xy = __ldg(&cov3Ds[6*i+1]);
    float xz = __ldg(&cov3Ds[6*i+2]), yy = __ldg(&cov3Ds[6*i+3]);
    float yz = __ldg(&cov3Ds[6*i+4]), zz = __ldg(&cov3Ds[6*i+5]);

    float j00 = fx * invz;
    float j02 = -fx * txn * invz * invz;
    float j11 = fy * invz;
    float j12 = -fy * tyn * invz * invz;

    float M00 = j00*xx + j02*xz;
    float M01 = j00*xy + j02*yz;
    float M02 = j00*xz + j02*zz;
    float M11 = j11*yy + j12*yz;
    float M12 = j11*yz + j12*zz;

    float a = M00*j00 + M02*j02 + 0.3f;
    float b = M01*j11 + M02*j12;
    float c = M11*j11 + M12*j12 + 0.3f;

    float det = a*c - b*b;
    float invdet = 1.0f / det;
    float conA = c * invdet;
    float conB = -b * invdet;
    float conC = a * invdet;

    float mid = 0.5f * (a + c);
    float lam1 = mid + sqrtf(fmaxf(0.1f, mid*mid - det));

    bool valid = (z > NEARP) && (det > 0.0f);
    out_radii[i] = valid ? ceilf(3.0f * sqrtf(lam1)) : 0.0f;

    float op = __ldg(&opacities[i]);
    float cullR2 = -1.0f;
    if (valid) {
        float tt = op * 255.0f;
        if (tt > 1.0f) cullR2 = 2.0f * lam1 * logf(tt);
    }

    float colR = __ldg(&colors[3*i+0]);
    float colG = __ldg(&colors[3*i+1]);
    float colB = __ldg(&colors[3*i+2]);
    __half2 rg = __floats2half2_rn(colR, colG);

    g_p[i] = make_float4(px, py, -0.5f*LOG2E*conA, -LOG2E*conB);
    g_q[i] = make_float4(-0.5f*LOG2E*conC, op,
                         __uint_as_float(half2_bits(rg)), colB);

    if (cullR2 >= 0.0f) {
        int bkt = (int)((z - 2.0f) * 4.0f);
        bkt = (bkt < 0) ? 0 : ((bkt > CHUNKS-1) ? CHUNKS-1 : bkt);
        unsigned long long key =
            ((unsigned long long)__float_as_uint(z) << 32) | (unsigned)i;

        float r = sqrtf(cullR2);
        int tX0 = (int)floorf((px - r) * 0.0625f);
        int tX1 = (int)floorf((px + r) * 0.0625f);
        int tY0 = (int)floorf((py - r) * 0.0625f);
        int tY1 = (int)floorf((py + r) * 0.0625f);
        tX0 = (tX0 < 0) ? 0 : tX0;  tY0 = (tY0 < 0) ? 0 : tY0;
        tX1 = (tX1 > 7) ? 7 : tX1;  tY1 = (tY1 > 7) ? 7 : tY1;

        for (int ty = tY0; ty <= tY1; ty++) {
            for (int tx = tX0; tx <= tX1; tx++) {
                // exact rect-distance test (same test blend used before)
                float rx0 = (float)(tx * 16), rx1 = rx0 + 15.0f;
                float ry0 = (float)(ty * 16), ry1 = ry0 + 15.0f;
                float ddx = fmaxf(0.0f, fmaxf(rx0 - px, px - rx1));
                float ddy = fmaxf(0.0f, fmaxf(ry0 - py, py - ry1));
                if (ddx*ddx + ddy*ddy <= cullR2) {
                    int list = (bkt << 6) | (ty << 3) | tx;
                    unsigned slot = atomicAdd(&g_lcnt[list], 1u);
                    if (slot < LCAP) g_list[list][slot] = key;
                }
            }
        }
    }
}

// ===== Kernel 2: per-(tile,bucket) sort -> blend -> tile combine =====
__global__ void __launch_bounds__(256) blend_kernel(
        const float* __restrict__ bg,
        float* __restrict__ out_img) {
    __shared__ unsigned long long s_keys[LCAP];
    __shared__ float4 s_P[LCAP];
    __shared__ float4 s_Q[LCAP];
    __shared__ unsigned s_last;

    int t = threadIdx.x;
    int bx = blockIdx.x;

    float bg0 = __ldg(&bg[0]), bg1 = __ldg(&bg[1]), bg2 = __ldg(&bg[2]);

    int tile   = bx & (NTILE-1);
    int bucket = bx >> 6;
    int tx0 = (tile & 7) * 16;
    int ty0 = (tile >> 3) * 16;
    float X = (float)(tx0 + (t & 15));
    float Y = (float)(ty0 + (t >> 4));

    int n = (int)g_lcnt[bx];             // kernel boundary => coherent
    if (n > LCAP) n = LCAP;

    if (t < n) s_keys[t] = g_list[bx][t];
    __syncthreads();

    // rank-sort survivors by (zbits, original idx) == reference stable argsort
    if (t < n) {
        unsigned long long ki = s_keys[t];
        int rnk = 0;
        for (int j = 0; j < n; j++)
            rnk += (s_keys[j] < ki);
        int gi = (int)(ki & 0xFFFFFFFFu);
        s_P[rnk] = __ldg(&g_p[gi]);
        s_Q[rnk] = __ldg(&g_q[gi]);
    }
    __syncthreads();

    // blend front-to-back
    float T = 1.0f, accr = 0.0f, accg = 0.0f, accb = 0.0f;
    #pragma unroll 4
    for (int j = 0; j < n; j++) {
        float4 a = s_P[j];
        float4 q = s_Q[j];
        float dx = a.x - X;
        float dy = a.y - Y;
        float p2 = fmaf(dx, fmaf(a.z, dx, a.w*dy), q.x*dy*dy);
        float alpha = fminf(q.y * fast_exp2(p2), 0.99f);
        if (p2 > 0.0f || alpha < AMIN) alpha = 0.0f;
        float2 rg = __half22float2(bits_half2(__float_as_uint(q.z)));
        float wgt = alpha * T;
        accr = fmaf(wgt, rg.x, accr);
        accg = fmaf(wgt, rg.y, accg);
        accb = fmaf(wgt, q.w,  accb);
        T = fmaf(-alpha, T, T);
    }

    int p = (ty0 + (t >> 4)) * HW + tx0 + (t & 15);
    g_part[bucket][p] = make_float4(accr, accg, accb, T);

    // last arriving bucket-CTA of this tile folds the partials (no spinning)
    __syncthreads();
    if (t == 0) {
        __threadfence();   // release: partial stores visible before count
        unsigned old = atomicAdd(&g_tile_cnt[tile], 1u);
        s_last = ((old & (CHUNKS-1u)) == CHUNKS-1u) ? 1u : 0u;
    }
    __syncthreads();

    if (s_last) {
        __threadfence();   // acquire: all partials visible
        float Tc = 1.0f, r = 0.0f, g = 0.0f, b = 0.0f;
        #pragma unroll
        for (int k = 0; k < CHUNKS; k++) {
            float4 c;
            if (k == bucket) c = make_float4(accr, accg, accb, T);
            else             c = __ldcg(&g_part[k][p]);
            r = fmaf(Tc, c.x, r);
            g = fmaf(Tc, c.y, g);
            b = fmaf(Tc, c.z, b);
            Tc *= c.w;
        }
        out_img[p]           = fmaf(Tc, bg0, r);
        out_img[HW*HW + p]   = fmaf(Tc, bg1, g);
        out_img[2*HW*HW + p] = fmaf(Tc, bg2, b);
    }

    // provably-last CTA resets list counters for next graph replay
    if (t == 0) {
        unsigned old = atomicAdd(&g_done, 1u);
        if ((old & (unsigned)(NCTA2-1)) == (unsigned)(NCTA2-1)) s_last = 2u;
        else s_last = 0u;
    }
    __syncthreads();
    if (s_last == 2u) {
        for (int k = t; k < NCTA2; k += 256) g_lcnt[k] = 0u;
    }
}

extern "C" void kernel_launch(void* const* d_in, const int* in_sizes, int n_in,
                              void* d_out, int out_size) {
    const float* means3D   = (const float*)d_in[0];
    const float* colors    = (const float*)d_in[1];
    const float* opacities = (const float*)d_in[2];
    const float* cov3Ds    = (const float*)d_in[3];
    const float* bg        = (const float*)d_in[4];
    float* out = (float*)d_out;
    float* out_img   = out;              // 3*128*128
    float* out_radii = out + 3*HW*HW;    // 2048

    prep_kernel<<<8, 256>>>(means3D, colors, opacities, cov3Ds, out_radii);
    blend_kernel<<<NCTA2, 256>>>(bg, out_img);
}